// round 5
// baseline (speedup 1.0000x reference)
#include <cuda_runtime.h>
#include <cstdint>

#define MAX_NODES 50000
#define MAX_EDGES 5000
#define MAX_NNZ   300000
#define DIM       256
#define DIM4      64
#define SCAN_TILE 1024
#define MAX_BLK_E ((MAX_EDGES + SCAN_TILE - 1) / SCAN_TILE)
#define MAX_BLK_N ((MAX_NODES + SCAN_TILE - 1) / SCAN_TILE)

// ---------------- static device scratch -------------------------------------
__device__ int   g_is64;
__device__ int   g_nidx[MAX_NNZ];
__device__ int   g_eidx[MAX_NNZ];
__device__ int   g_deg_n[MAX_NODES];
__device__ int   g_deg_e[MAX_EDGES];
__device__ int   g_off_e[MAX_EDGES + 1];
__device__ int   g_cur_e[MAX_EDGES];
__device__ int   g_off_n[MAX_NODES + 1];
__device__ int   g_cur_n[MAX_NODES];
__device__ int   g_e_nodes[MAX_NNZ];
__device__ int   g_n_edges[MAX_NNZ];
__device__ float g_eagg[MAX_EDGES * DIM];
__device__ float g_ew[MAX_EDGES * DIM];
__device__ int   g_bsum_e[MAX_BLK_E];
__device__ int   g_bsum_n[MAX_BLK_N];

// ---------------- software grid barrier --------------------------------------
__device__ unsigned g_cnt = 0;
__device__ unsigned g_gen = 0;

__device__ __forceinline__ void gbar(unsigned nb) {
    __syncthreads();
    if (threadIdx.x == 0) {
        volatile unsigned* vgen = &g_gen;
        unsigned gen = *vgen;
        __threadfence();
        unsigned t = atomicAdd(&g_cnt, 1u);
        if (t == nb - 1u) {
            g_cnt = 0u;
            __threadfence();
            *vgen = gen + 1u;
        } else {
            while (*vgen == gen) __nanosleep(64);
        }
        __threadfence();
    }
    __syncthreads();
}

__device__ __forceinline__ int warp_incl_scan(int v, int lane) {
#pragma unroll
    for (int o = 1; o < 32; o <<= 1) {
        int t = __shfl_up_sync(0xffffffffu, v, o);
        if (lane >= o) v += t;
    }
    return v;
}

// ---------------- the megakernel ---------------------------------------------
__global__ void __launch_bounds__(256, 2)
k_mega(const float4* __restrict__ x4, const unsigned int* __restrict__ raw,
       const float* __restrict__ W, const float4* __restrict__ b4,
       float4* __restrict__ out4,
       int nn, int nnz, int ne, int nbe, int nbn, int nblocks) {
    __shared__ __align__(16) char shmem[16 * 65 * 4 * 2];   // gemm As+Bs / scan sh
    __shared__ int wbase[8];

    const int tid = threadIdx.x;
    const int bid = blockIdx.x;
    const int gtid = bid * 256 + tid;
    const int nthreads = nblocks * 256;
    const int lane = tid & 31;
    const int wid = tid >> 5;
    const int nhalf = (nnz + 1) / 2;

    // ===== Phase A: zero histograms; last block detects int64 vs int32 ======
    for (int i = gtid; i < nn; i += nthreads) g_deg_n[i] = 0;
    for (int i = gtid; i < ne; i += nthreads) g_deg_e[i] = 0;
    if (bid == nblocks - 1 && tid < 32) {
        int nw = 2 * nnz;
        if (nw > 512) nw = 512;
        int bad = 0;
        for (int i = 1 + 2 * tid; i < nw; i += 64)
            if (raw[i] != 0u) bad = 1;
        bad = __any_sync(0xffffffffu, bad);
        if (tid == 0) g_is64 = !bad;
    }
    gbar(nblocks);

    // ===== Phase B: convert indices + degree histograms (2 per thread) ======
    {
        const int is64 = g_is64;
        for (int t = gtid; t < nhalf; t += nthreads) {
            int i0 = 2 * t;
            bool has2 = (i0 + 1 < nnz);
            int n0, n1 = 0, e0, e1 = 0;
            if (is64) {
                if (has2) {
                    uint4 vn = ((const uint4*)raw)[t];
                    uint4 ve = ((const uint4*)(raw + 2 * (size_t)nnz))[t];
                    n0 = (int)vn.x; n1 = (int)vn.z;
                    e0 = (int)ve.x; e1 = (int)ve.z;
                } else {
                    n0 = (int)raw[2 * (size_t)i0];
                    e0 = (int)raw[2 * ((size_t)nnz + i0)];
                }
            } else {
                if (has2) {
                    uint2 vn = ((const uint2*)raw)[t];
                    uint2 ve = ((const uint2*)(raw + (size_t)nnz))[t];
                    n0 = (int)vn.x; n1 = (int)vn.y;
                    e0 = (int)ve.x; e1 = (int)ve.y;
                } else {
                    n0 = (int)raw[i0];
                    e0 = (int)raw[(size_t)nnz + i0];
                }
            }
            if (n0 < 0) n0 = 0; if (n0 >= nn) n0 = nn - 1;
            if (e0 < 0) e0 = 0; if (e0 >= ne) e0 = ne - 1;
            if (has2) {
                if (n1 < 0) n1 = 0; if (n1 >= nn) n1 = nn - 1;
                if (e1 < 0) e1 = 0; if (e1 >= ne) e1 = ne - 1;
                ((int2*)g_nidx)[t] = make_int2(n0, n1);
                ((int2*)g_eidx)[t] = make_int2(e0, e1);
                atomicAdd(&g_deg_n[n0], 1);
                atomicAdd(&g_deg_n[n1], 1);
                atomicAdd(&g_deg_e[e0], 1);
                atomicAdd(&g_deg_e[e1], 1);
            } else {
                g_nidx[i0] = n0;
                g_eidx[i0] = e0;
                atomicAdd(&g_deg_n[n0], 1);
                atomicAdd(&g_deg_e[e0], 1);
            }
        }
    }
    gbar(nblocks);

    // ===== Phase C1: per-tile sums ==========================================
    if (bid < nbe + nbn) {
        const int* deg; int n; int* bsum; int blk;
        if (bid < nbe) { deg = g_deg_e; n = ne; bsum = g_bsum_e; blk = bid; }
        else           { deg = g_deg_n; n = nn; bsum = g_bsum_n; blk = bid - nbe; }
        int base = blk * SCAN_TILE;
        int s = 0;
#pragma unroll
        for (int k = 0; k < 4; k++) {
            int i = base + tid + k * 256;
            if (i < n) s += deg[i];
        }
#pragma unroll
        for (int o = 16; o; o >>= 1) s += __shfl_down_sync(0xffffffffu, s, o);
        int* ws = (int*)shmem;
        if (lane == 0) ws[wid] = s;
        __syncthreads();
        if (tid == 0) {
            int v = 0;
#pragma unroll
            for (int w = 0; w < 8; w++) v += ws[w];
            bsum[blk] = v;
        }
    }
    gbar(nblocks);

    // ===== Phase C2: scan of block sums (block 0, two warps) ================
    if (bid == 0) {
        if (tid < 32) {
            int carry = 0;
            for (int c0 = 0; c0 < nbe; c0 += 32) {
                int i = c0 + lane;
                int v = (i < nbe) ? g_bsum_e[i] : 0;
                int inc = warp_incl_scan(v, lane);
                if (i < nbe) g_bsum_e[i] = carry + inc - v;
                carry += __shfl_sync(0xffffffffu, inc, 31);
            }
            if (lane == 0) g_off_e[ne] = carry;
        } else if (tid < 64) {
            int carry = 0;
            for (int c0 = 0; c0 < nbn; c0 += 32) {
                int i = c0 + lane;
                int v = (i < nbn) ? g_bsum_n[i] : 0;
                int inc = warp_incl_scan(v, lane);
                if (i < nbn) g_bsum_n[i] = carry + inc - v;
                carry += __shfl_sync(0xffffffffu, inc, 31);
            }
            if (lane == 0) g_off_n[nn] = carry;
        }
    }
    gbar(nblocks);

    // ===== Phase C3: per-tile exclusive scan ================================
    if (bid < nbe + nbn) {
        int* sh = (int*)shmem;
        const int* deg; int n; int* off; int* cur; int base0; int blk;
        if (bid < nbe) {
            deg = g_deg_e; n = ne; off = g_off_e; cur = g_cur_e;
            blk = bid; base0 = g_bsum_e[blk];
        } else {
            deg = g_deg_n; n = nn; off = g_off_n; cur = g_cur_n;
            blk = bid - nbe; base0 = g_bsum_n[blk];
        }
        int base = blk * SCAN_TILE;
#pragma unroll
        for (int k = 0; k < 4; k++) {
            int i = base + tid + k * 256;
            sh[tid + k * 256] = (i < n) ? deg[i] : 0;
        }
        __syncthreads();
        int v0 = sh[tid * 4], v1 = sh[tid * 4 + 1], v2 = sh[tid * 4 + 2], v3 = sh[tid * 4 + 3];
        int local = v0 + v1 + v2 + v3;
        int inc = warp_incl_scan(local, lane);
        if (lane == 31) wbase[wid] = inc;
        __syncthreads();
        if (tid == 0) {
            int run = 0;
#pragma unroll
            for (int w = 0; w < 8; w++) { int t = wbase[w]; wbase[w] = run; run += t; }
        }
        __syncthreads();
        int excl = base0 + wbase[wid] + inc - local;
        sh[tid * 4]     = excl;
        sh[tid * 4 + 1] = excl + v0;
        sh[tid * 4 + 2] = excl + v0 + v1;
        sh[tid * 4 + 3] = excl + v0 + v1 + v2;
        __syncthreads();
#pragma unroll
        for (int k = 0; k < 4; k++) {
            int i = base + tid + k * 256;
            if (i < n) { int val = sh[tid + k * 256]; off[i] = val; cur[i] = val; }
        }
    }
    gbar(nblocks);

    // ===== Phase D: CSR scatter =============================================
    for (int t = gtid; t < nhalf; t += nthreads) {
        int i0 = 2 * t;
        if (i0 + 1 < nnz) {
            int2 nv = ((const int2*)g_nidx)[t];
            int2 ev = ((const int2*)g_eidx)[t];
            int p0 = atomicAdd(&g_cur_e[ev.x], 1);
            int p1 = atomicAdd(&g_cur_e[ev.y], 1);
            g_e_nodes[p0] = nv.x;
            g_e_nodes[p1] = nv.y;
            int q0 = atomicAdd(&g_cur_n[nv.x], 1);
            int q1 = atomicAdd(&g_cur_n[nv.y], 1);
            g_n_edges[q0] = ev.x;
            g_n_edges[q1] = ev.y;
        } else {
            int n = g_nidx[i0];
            int e = g_eidx[i0];
            int p = atomicAdd(&g_cur_e[e], 1);
            g_e_nodes[p] = n;
            int q = atomicAdd(&g_cur_n[n], 1);
            g_n_edges[q] = e;
        }
    }
    gbar(nblocks);

    // ===== Phase E: edge aggregation ========================================
    {
        int c = lane;
        for (int e = bid * 8 + wid; e < ne; e += nblocks * 8) {
            int s = g_off_e[e];
            int t = g_off_e[e + 1];
            float4 a0 = make_float4(0.f, 0.f, 0.f, 0.f);
            float4 a1 = make_float4(0.f, 0.f, 0.f, 0.f);
            int j = s;
#pragma unroll 2
            for (; j + 2 <= t; j += 2) {
                int n0 = g_e_nodes[j];
                int n1 = g_e_nodes[j + 1];
                float4 v0 = __ldg(&x4[(size_t)n0 * DIM4 + c]);
                float4 v1 = __ldg(&x4[(size_t)n0 * DIM4 + c + 32]);
                float4 w0 = __ldg(&x4[(size_t)n1 * DIM4 + c]);
                float4 w1 = __ldg(&x4[(size_t)n1 * DIM4 + c + 32]);
                a0.x += v0.x + w0.x; a0.y += v0.y + w0.y;
                a0.z += v0.z + w0.z; a0.w += v0.w + w0.w;
                a1.x += v1.x + w1.x; a1.y += v1.y + w1.y;
                a1.z += v1.z + w1.z; a1.w += v1.w + w1.w;
            }
            if (j < t) {
                int n0 = g_e_nodes[j];
                float4 v0 = __ldg(&x4[(size_t)n0 * DIM4 + c]);
                float4 v1 = __ldg(&x4[(size_t)n0 * DIM4 + c + 32]);
                a0.x += v0.x; a0.y += v0.y; a0.z += v0.z; a0.w += v0.w;
                a1.x += v1.x; a1.y += v1.y; a1.z += v1.z; a1.w += v1.w;
            }
            float binv = (t > s) ? 1.0f / (float)(t - s) : 0.0f;
            a0.x *= binv; a0.y *= binv; a0.z *= binv; a0.w *= binv;
            a1.x *= binv; a1.y *= binv; a1.z *= binv; a1.w *= binv;
            float4* dst = reinterpret_cast<float4*>(g_eagg) + (size_t)e * DIM4;
            dst[c] = a0;
            dst[c + 32] = a1;
        }
    }
    gbar(nblocks);

    // ===== Phase F: GEMM ew = eagg @ W ======================================
    {
        float* As = (float*)shmem;            // [16][65]
        float* Bs = As + 16 * 65;             // [16][65]
        int mt = (ne + 63) / 64;
        int ntiles = mt * 4;
        int tx = tid & 15, ty = tid >> 4;
        for (int tile = bid; tile < ntiles; tile += nblocks) {
            int m0 = (tile >> 2) * 64;
            int n0 = (tile & 3) * 64;
            float acc[4][4] = {};
            for (int k0 = 0; k0 < DIM; k0 += 16) {
#pragma unroll
                for (int p = 0; p < 4; p++) {
                    int idx = tid + p * 256;
                    int r = idx >> 4, kk = idx & 15;
                    int row = m0 + r;
                    As[kk * 65 + r] = (row < ne) ? g_eagg[(size_t)row * DIM + k0 + kk] : 0.0f;
                }
#pragma unroll
                for (int p = 0; p < 4; p++) {
                    int idx = tid + p * 256;
                    int kk = idx >> 6, cc = idx & 63;
                    Bs[kk * 65 + cc] = W[(size_t)(k0 + kk) * DIM + n0 + cc];
                }
                __syncthreads();
#pragma unroll
                for (int kk = 0; kk < 16; kk++) {
                    float a[4], bv[4];
#pragma unroll
                    for (int i = 0; i < 4; i++) a[i] = As[kk * 65 + ty + 16 * i];
#pragma unroll
                    for (int j = 0; j < 4; j++) bv[j] = Bs[kk * 65 + tx + 16 * j];
#pragma unroll
                    for (int i = 0; i < 4; i++)
#pragma unroll
                        for (int j = 0; j < 4; j++)
                            acc[i][j] += a[i] * bv[j];
                }
                __syncthreads();
            }
#pragma unroll
            for (int i = 0; i < 4; i++) {
                int row = m0 + ty + 16 * i;
                if (row < ne) {
#pragma unroll
                    for (int j = 0; j < 4; j++)
                        g_ew[(size_t)row * DIM + n0 + tx + 16 * j] = acc[i][j];
                }
            }
        }
    }
    gbar(nblocks);

    // ===== Phase G: node aggregation + epilogue =============================
    {
        int c = lane;
        const float4* ew4 = reinterpret_cast<const float4*>(g_ew);
        float4 b0 = __ldg(&b4[c]);
        float4 b1 = __ldg(&b4[c + 32]);
        for (int node = bid * 8 + wid; node < nn; node += nblocks * 8) {
            int s = g_off_n[node];
            int t = g_off_n[node + 1];
            float4 a0 = make_float4(0.f, 0.f, 0.f, 0.f);
            float4 a1 = make_float4(0.f, 0.f, 0.f, 0.f);
            int j = s;
#pragma unroll 2
            for (; j + 2 <= t; j += 2) {
                int e0 = g_n_edges[j];
                int e1 = g_n_edges[j + 1];
                float4 v0 = ew4[(size_t)e0 * DIM4 + c];
                float4 v1 = ew4[(size_t)e0 * DIM4 + c + 32];
                float4 w0 = ew4[(size_t)e1 * DIM4 + c];
                float4 w1 = ew4[(size_t)e1 * DIM4 + c + 32];
                a0.x += v0.x + w0.x; a0.y += v0.y + w0.y;
                a0.z += v0.z + w0.z; a0.w += v0.w + w0.w;
                a1.x += v1.x + w1.x; a1.y += v1.y + w1.y;
                a1.z += v1.z + w1.z; a1.w += v1.w + w1.w;
            }
            if (j < t) {
                int e0 = g_n_edges[j];
                float4 v0 = ew4[(size_t)e0 * DIM4 + c];
                float4 v1 = ew4[(size_t)e0 * DIM4 + c + 32];
                a0.x += v0.x; a0.y += v0.y; a0.z += v0.z; a0.w += v0.w;
                a1.x += v1.x; a1.y += v1.y; a1.z += v1.z; a1.w += v1.w;
            }
            float dinv = (t > s) ? 1.0f / (float)(t - s) : 0.0f;
            float4 r0, r1;
            r0.x = fmaxf(fmaf(a0.x, dinv, b0.x), 0.0f);
            r0.y = fmaxf(fmaf(a0.y, dinv, b0.y), 0.0f);
            r0.z = fmaxf(fmaf(a0.z, dinv, b0.z), 0.0f);
            r0.w = fmaxf(fmaf(a0.w, dinv, b0.w), 0.0f);
            r1.x = fmaxf(fmaf(a1.x, dinv, b1.x), 0.0f);
            r1.y = fmaxf(fmaf(a1.y, dinv, b1.y), 0.0f);
            r1.z = fmaxf(fmaf(a1.z, dinv, b1.z), 0.0f);
            r1.w = fmaxf(fmaf(a1.w, dinv, b1.w), 0.0f);
            out4[(size_t)node * DIM4 + c] = r0;
            out4[(size_t)node * DIM4 + c + 32] = r1;
        }
    }
}

// ---------------- launch ------------------------------------------------------
extern "C" void kernel_launch(void* const* d_in, const int* in_sizes, int n_in,
                              void* d_out, int out_size) {
    const float*        x  = (const float*)d_in[0];
    const unsigned int* ei = (const unsigned int*)d_in[1];
    const float*        W  = (const float*)d_in[2];
    const float*        b  = (const float*)d_in[3];

    int nn  = in_sizes[0] / DIM;
    int nnz = in_sizes[1] / 2;
    int ne  = MAX_EDGES;
    if (nn  > MAX_NODES) nn  = MAX_NODES;
    if (nnz > MAX_NNZ)   nnz = MAX_NNZ;

    int nbe = (ne + SCAN_TILE - 1) / SCAN_TILE;
    int nbn = (nn + SCAN_TILE - 1) / SCAN_TILE;

    int sms = 148;
    int dev = 0;
    cudaGetDevice(&dev);
    cudaDeviceGetAttribute(&sms, cudaDevAttrMultiProcessorCount, dev);
    int nblocks = 2 * sms;           // __launch_bounds__(256,2) guarantees residency

    k_mega<<<nblocks, 256>>>((const float4*)x, ei, W, (const float4*)b,
                             (float4*)d_out, nn, nnz, ne, nbe, nbn, nblocks);
}

// round 6
// speedup vs baseline: 1.3003x; 1.3003x over previous
#include <cuda_runtime.h>
#include <cuda_fp16.h>
#include <cstdint>

#define MAX_NODES 50000
#define MAX_EDGES 5000
#define MAX_NNZ   300000
#define DIM       256
#define DIM4      64

#define SCAN_TILE 1024
#define MAX_BLK_E ((MAX_EDGES + SCAN_TILE - 1) / SCAN_TILE)
#define MAX_BLK_N ((MAX_NODES + SCAN_TILE - 1) / SCAN_TILE)

// ---------------- static device scratch -------------------------------------
__device__ int    g_is64;
__device__ int    g_tick;
__device__ int    g_nidx[MAX_NNZ];
__device__ int    g_eidx[MAX_NNZ];
__device__ int    g_deg_n[MAX_NODES];
__device__ int    g_deg_e[MAX_EDGES];
__device__ int    g_off_e[MAX_EDGES + 1];
__device__ int    g_cur_e[MAX_EDGES];
__device__ int    g_off_n[MAX_NODES + 1];
__device__ int    g_cur_n[MAX_NODES];
__device__ int    g_e_nodes[MAX_NNZ];
__device__ int    g_n_edges[MAX_NNZ];
__device__ float  g_eagg[MAX_EDGES * DIM];
__device__ __half g_ew[MAX_EDGES * DIM];     // fp16 intermediate (read 300k times)
__device__ int    g_bsum_e[MAX_BLK_E];
__device__ int    g_bsum_n[MAX_BLK_N];

// ---------------- init: zero histograms + tick, detect dtype ----------------
__global__ void k_init(const unsigned int* __restrict__ raw, int nnz,
                       int nn, int ne) {
    if ((int)blockIdx.x == (int)gridDim.x - 1) {
        int tid = threadIdx.x;
        if (tid < 32) {
            int nw = 2 * nnz;
            if (nw > 512) nw = 512;
            int bad = 0;
            for (int i = 1 + 2 * tid; i < nw; i += 64)
                if (raw[i] != 0u) bad = 1;
            bad = __any_sync(0xffffffffu, bad);
            if (tid == 0) { g_is64 = !bad; g_tick = 0; }
        }
        return;
    }
    int i = blockIdx.x * blockDim.x + threadIdx.x;
    if (i < nn) g_deg_n[i] = 0;
    if (i < ne) g_deg_e[i] = 0;
}

// ---------------- convert indices + degree histograms (2 per thread) --------
__global__ void k_convert(const unsigned int* __restrict__ raw, int nnz,
                          int nn, int ne) {
    int tid = blockIdx.x * blockDim.x + threadIdx.x;
    int i0 = 2 * tid;
    if (i0 >= nnz) return;
    bool has2 = (i0 + 1 < nnz);
    int n0, n1 = 0, e0, e1 = 0;
    if (g_is64) {
        if (has2) {
            uint4 vn = ((const uint4*)raw)[tid];
            uint4 ve = ((const uint4*)(raw + 2 * (size_t)nnz))[tid];
            n0 = (int)vn.x; n1 = (int)vn.z;
            e0 = (int)ve.x; e1 = (int)ve.z;
        } else {
            n0 = (int)raw[2 * (size_t)i0];
            e0 = (int)raw[2 * ((size_t)nnz + i0)];
        }
    } else {
        if (has2) {
            uint2 vn = ((const uint2*)raw)[tid];
            uint2 ve = ((const uint2*)(raw + (size_t)nnz))[tid];
            n0 = (int)vn.x; n1 = (int)vn.y;
            e0 = (int)ve.x; e1 = (int)ve.y;
        } else {
            n0 = (int)raw[i0];
            e0 = (int)raw[(size_t)nnz + i0];
        }
    }
    if (n0 < 0) n0 = 0; if (n0 >= nn) n0 = nn - 1;
    if (e0 < 0) e0 = 0; if (e0 >= ne) e0 = ne - 1;
    if (has2) {
        if (n1 < 0) n1 = 0; if (n1 >= nn) n1 = nn - 1;
        if (e1 < 0) e1 = 0; if (e1 >= ne) e1 = ne - 1;
        ((int2*)g_nidx)[tid] = make_int2(n0, n1);
        ((int2*)g_eidx)[tid] = make_int2(e0, e1);
        atomicAdd(&g_deg_n[n0], 1);
        atomicAdd(&g_deg_n[n1], 1);
        atomicAdd(&g_deg_e[e0], 1);
        atomicAdd(&g_deg_e[e1], 1);
    } else {
        g_nidx[i0] = n0;
        g_eidx[i0] = e0;
        atomicAdd(&g_deg_n[n0], 1);
        atomicAdd(&g_deg_e[e0], 1);
    }
}

// ---------------- scan phase 1 + fused block-sum scan (last block) ----------
__device__ __forceinline__ int warp_incl_scan(int v, int lane) {
#pragma unroll
    for (int o = 1; o < 32; o <<= 1) {
        int t = __shfl_up_sync(0xffffffffu, v, o);
        if (lane >= o) v += t;
    }
    return v;
}

__global__ void k_scan_p1(int nn, int ne, int nbe, int nbn) {
    const int* deg; int n; int* bsum; int blk;
    if ((int)blockIdx.x < nbe) { deg = g_deg_e; n = ne; bsum = g_bsum_e; blk = blockIdx.x; }
    else                       { deg = g_deg_n; n = nn; bsum = g_bsum_n; blk = blockIdx.x - nbe; }
    int base = blk * SCAN_TILE;
    int tid = threadIdx.x;            // 256 threads
    int s = 0;
#pragma unroll
    for (int k = 0; k < 4; k++) {
        int i = base + tid + k * 256;
        if (i < n) s += deg[i];
    }
#pragma unroll
    for (int o = 16; o; o >>= 1) s += __shfl_down_sync(0xffffffffu, s, o);
    __shared__ int ws[8];
    __shared__ int is_last;
    if ((tid & 31) == 0) ws[tid >> 5] = s;
    __syncthreads();
    if (tid == 0) {
        int v = 0;
#pragma unroll
        for (int w = 0; w < 8; w++) v += ws[w];
        bsum[blk] = v;
        __threadfence();
        int t = atomicAdd(&g_tick, 1);
        is_last = (t == nbe + nbn - 1);
    }
    __syncthreads();
    if (!is_last) return;
    int lane = tid & 31;
    if (tid < 32) {
        int carry = 0;
        for (int c0 = 0; c0 < nbe; c0 += 32) {
            int i = c0 + lane;
            int v = (i < nbe) ? __ldcg(&g_bsum_e[i]) : 0;
            int inc = warp_incl_scan(v, lane);
            if (i < nbe) g_bsum_e[i] = carry + inc - v;
            carry += __shfl_sync(0xffffffffu, inc, 31);
        }
        if (lane == 0) g_off_e[ne] = carry;
    } else if (tid < 64) {
        int carry = 0;
        for (int c0 = 0; c0 < nbn; c0 += 32) {
            int i = c0 + lane;
            int v = (i < nbn) ? __ldcg(&g_bsum_n[i]) : 0;
            int inc = warp_incl_scan(v, lane);
            if (i < nbn) g_bsum_n[i] = carry + inc - v;
            carry += __shfl_sync(0xffffffffu, inc, 31);
        }
        if (lane == 0) g_off_n[nn] = carry;
    }
}

// ---------------- scan phase 3: per-tile exclusive scan ----------------------
__global__ void k_scan_p3(int nn, int ne, int nbe) {
    __shared__ int sh[SCAN_TILE];
    __shared__ int wbase[8];
    const int* deg; int n; int* off; int* cur; int base0; int blk;
    if ((int)blockIdx.x < nbe) {
        deg = g_deg_e; n = ne; off = g_off_e; cur = g_cur_e;
        blk = blockIdx.x; base0 = g_bsum_e[blk];
    } else {
        deg = g_deg_n; n = nn; off = g_off_n; cur = g_cur_n;
        blk = blockIdx.x - nbe; base0 = g_bsum_n[blk];
    }
    int base = blk * SCAN_TILE;
    int tid = threadIdx.x;
#pragma unroll
    for (int k = 0; k < 4; k++) {
        int i = base + tid + k * 256;
        sh[tid + k * 256] = (i < n) ? deg[i] : 0;
    }
    __syncthreads();
    int v0 = sh[tid * 4], v1 = sh[tid * 4 + 1], v2 = sh[tid * 4 + 2], v3 = sh[tid * 4 + 3];
    int local = v0 + v1 + v2 + v3;
    int lane = tid & 31, wid = tid >> 5;
    int inc = warp_incl_scan(local, lane);
    if (lane == 31) wbase[wid] = inc;
    __syncthreads();
    if (tid == 0) {
        int run = 0;
#pragma unroll
        for (int w = 0; w < 8; w++) { int t = wbase[w]; wbase[w] = run; run += t; }
    }
    __syncthreads();
    int excl = base0 + wbase[wid] + inc - local;
    sh[tid * 4]     = excl;
    sh[tid * 4 + 1] = excl + v0;
    sh[tid * 4 + 2] = excl + v0 + v1;
    sh[tid * 4 + 3] = excl + v0 + v1 + v2;
    __syncthreads();
#pragma unroll
    for (int k = 0; k < 4; k++) {
        int i = base + tid + k * 256;
        if (i < n) { int val = sh[tid + k * 256]; off[i] = val; cur[i] = val; }
    }
}

// ---------------- CSR fill (2 incidences per thread) -------------------------
__global__ void k_scatter(int nnz) {
    int tid = blockIdx.x * blockDim.x + threadIdx.x;
    int i0 = 2 * tid;
    if (i0 >= nnz) return;
    if (i0 + 1 < nnz) {
        int2 nv = ((const int2*)g_nidx)[tid];
        int2 ev = ((const int2*)g_eidx)[tid];
        int p0 = atomicAdd(&g_cur_e[ev.x], 1);
        int p1 = atomicAdd(&g_cur_e[ev.y], 1);
        g_e_nodes[p0] = nv.x;
        g_e_nodes[p1] = nv.y;
        int q0 = atomicAdd(&g_cur_n[nv.x], 1);
        int q1 = atomicAdd(&g_cur_n[nv.y], 1);
        g_n_edges[q0] = ev.x;
        g_n_edges[q1] = ev.y;
    } else {
        int n = g_nidx[i0];
        int e = g_eidx[i0];
        int p = atomicAdd(&g_cur_e[e], 1);
        g_e_nodes[p] = n;
        int q = atomicAdd(&g_cur_n[n], 1);
        g_n_edges[q] = e;
    }
}

// ---------------- edge aggregation (fp32 x) ----------------------------------
__global__ void k_edge_agg(const float4* __restrict__ x4, int ne) {
    int e = blockIdx.x * 8 + (threadIdx.x >> 5);
    if (e >= ne) return;
    int c = threadIdx.x & 31;
    int s = g_off_e[e];
    int t = g_off_e[e + 1];
    float4 a0 = make_float4(0.f, 0.f, 0.f, 0.f);
    float4 a1 = make_float4(0.f, 0.f, 0.f, 0.f);
    int j = s;
#pragma unroll 2
    for (; j + 2 <= t; j += 2) {
        int n0 = g_e_nodes[j];
        int n1 = g_e_nodes[j + 1];
        float4 v0 = __ldg(&x4[(size_t)n0 * DIM4 + c]);
        float4 v1 = __ldg(&x4[(size_t)n0 * DIM4 + c + 32]);
        float4 w0 = __ldg(&x4[(size_t)n1 * DIM4 + c]);
        float4 w1 = __ldg(&x4[(size_t)n1 * DIM4 + c + 32]);
        a0.x += v0.x + w0.x; a0.y += v0.y + w0.y;
        a0.z += v0.z + w0.z; a0.w += v0.w + w0.w;
        a1.x += v1.x + w1.x; a1.y += v1.y + w1.y;
        a1.z += v1.z + w1.z; a1.w += v1.w + w1.w;
    }
    if (j < t) {
        int n0 = g_e_nodes[j];
        float4 v0 = __ldg(&x4[(size_t)n0 * DIM4 + c]);
        float4 v1 = __ldg(&x4[(size_t)n0 * DIM4 + c + 32]);
        a0.x += v0.x; a0.y += v0.y; a0.z += v0.z; a0.w += v0.w;
        a1.x += v1.x; a1.y += v1.y; a1.z += v1.z; a1.w += v1.w;
    }
    float binv = (t > s) ? 1.0f / (float)(t - s) : 0.0f;
    a0.x *= binv; a0.y *= binv; a0.z *= binv; a0.w *= binv;
    a1.x *= binv; a1.y *= binv; a1.z *= binv; a1.w *= binv;
    float4* dst = reinterpret_cast<float4*>(g_eagg) + (size_t)e * DIM4;
    dst[c] = a0;
    dst[c + 32] = a1;
}

// ---------------- GEMM: ew[M,256] = eagg @ W, stored as fp16 -----------------
__global__ void k_gemm(const float* __restrict__ W, int M) {
    __shared__ float As[16][65];
    __shared__ float Bs[16][65];
    int m0 = blockIdx.x * 64;
    int n0 = blockIdx.y * 64;
    int tid = threadIdx.x;          // 256 threads
    int tx = tid & 15, ty = tid >> 4;
    float acc[4][4] = {};
    for (int k0 = 0; k0 < DIM; k0 += 16) {
#pragma unroll
        for (int p = 0; p < 4; p++) {
            int idx = tid + p * 256;
            int r = idx >> 4, kk = idx & 15;
            int row = m0 + r;
            As[kk][r] = (row < M) ? g_eagg[(size_t)row * DIM + k0 + kk] : 0.0f;
        }
#pragma unroll
        for (int p = 0; p < 4; p++) {
            int idx = tid + p * 256;
            int kk = idx >> 6, cc = idx & 63;
            Bs[kk][cc] = W[(size_t)(k0 + kk) * DIM + n0 + cc];
        }
        __syncthreads();
#pragma unroll
        for (int kk = 0; kk < 16; kk++) {
            float a[4], bv[4];
#pragma unroll
            for (int i = 0; i < 4; i++) a[i] = As[kk][ty + 16 * i];
#pragma unroll
            for (int j = 0; j < 4; j++) bv[j] = Bs[kk][tx + 16 * j];
#pragma unroll
            for (int i = 0; i < 4; i++)
#pragma unroll
                for (int j = 0; j < 4; j++)
                    acc[i][j] += a[i] * bv[j];
        }
        __syncthreads();
    }
#pragma unroll
    for (int i = 0; i < 4; i++) {
        int row = m0 + ty + 16 * i;
        if (row < M) {
#pragma unroll
            for (int j = 0; j < 4; j++)
                g_ew[(size_t)row * DIM + n0 + tx + 16 * j] = __float2half_rn(acc[i][j]);
        }
    }
}

// ---------------- node aggregation + epilogue (fp16 gather, fp32 accum) ------
// 32 threads/node; each thread owns one 16B chunk = 8 halves of the 256-dim row.
__global__ void k_node_agg(const float* __restrict__ b,
                           float4* __restrict__ out4, int nn) {
    int node = blockIdx.x * 8 + (threadIdx.x >> 5);
    if (node >= nn) return;
    int c = threadIdx.x & 31;                 // chunk id: halves [8c, 8c+8)
    int s = g_off_n[node];
    int t = g_off_n[node + 1];
    const uint4* ew16 = reinterpret_cast<const uint4*>(g_ew);
    float acc[8] = {};
    int j = s;
#pragma unroll 2
    for (; j + 2 <= t; j += 2) {
        int e0 = g_n_edges[j];
        int e1 = g_n_edges[j + 1];
        uint4 u = ew16[(size_t)e0 * 32 + c];
        uint4 v = ew16[(size_t)e1 * 32 + c];
        const __half2* hu = reinterpret_cast<const __half2*>(&u);
        const __half2* hv = reinterpret_cast<const __half2*>(&v);
#pragma unroll
        for (int q = 0; q < 4; q++) {
            float2 fu = __half22float2(hu[q]);
            float2 fv = __half22float2(hv[q]);
            acc[2 * q]     += fu.x + fv.x;
            acc[2 * q + 1] += fu.y + fv.y;
        }
    }
    if (j < t) {
        int e0 = g_n_edges[j];
        uint4 u = ew16[(size_t)e0 * 32 + c];
        const __half2* hu = reinterpret_cast<const __half2*>(&u);
#pragma unroll
        for (int q = 0; q < 4; q++) {
            float2 fu = __half22float2(hu[q]);
            acc[2 * q]     += fu.x;
            acc[2 * q + 1] += fu.y;
        }
    }
    float dinv = (t > s) ? 1.0f / (float)(t - s) : 0.0f;
    float4 bb0 = __ldg((const float4*)(b + 8 * c));
    float4 bb1 = __ldg((const float4*)(b + 8 * c + 4));
    float4 r0, r1;
    r0.x = fmaxf(fmaf(acc[0], dinv, bb0.x), 0.0f);
    r0.y = fmaxf(fmaf(acc[1], dinv, bb0.y), 0.0f);
    r0.z = fmaxf(fmaf(acc[2], dinv, bb0.z), 0.0f);
    r0.w = fmaxf(fmaf(acc[3], dinv, bb0.w), 0.0f);
    r1.x = fmaxf(fmaf(acc[4], dinv, bb1.x), 0.0f);
    r1.y = fmaxf(fmaf(acc[5], dinv, bb1.y), 0.0f);
    r1.z = fmaxf(fmaf(acc[6], dinv, bb1.z), 0.0f);
    r1.w = fmaxf(fmaf(acc[7], dinv, bb1.w), 0.0f);
    out4[(size_t)node * DIM4 + 2 * c]     = r0;
    out4[(size_t)node * DIM4 + 2 * c + 1] = r1;
}

// ---------------- launch ------------------------------------------------------
extern "C" void kernel_launch(void* const* d_in, const int* in_sizes, int n_in,
                              void* d_out, int out_size) {
    const float*        x  = (const float*)d_in[0];
    const unsigned int* ei = (const unsigned int*)d_in[1];
    const float*        W  = (const float*)d_in[2];
    const float*        b  = (const float*)d_in[3];

    int nn  = in_sizes[0] / DIM;
    int nnz = in_sizes[1] / 2;
    int ne  = MAX_EDGES;
    if (nn  > MAX_NODES) nn  = MAX_NODES;
    if (nnz > MAX_NNZ)   nnz = MAX_NNZ;

    int nmax = nn > ne ? nn : ne;
    int nbe = (ne + SCAN_TILE - 1) / SCAN_TILE;
    int nbn = (nn + SCAN_TILE - 1) / SCAN_TILE;
    int nhalf = (nnz + 1) / 2;

    k_init<<<(nmax + 255) / 256 + 1, 256>>>(ei, nnz, nn, ne);
    k_convert<<<(nhalf + 255) / 256, 256>>>(ei, nnz, nn, ne);
    k_scan_p1<<<nbe + nbn, 256>>>(nn, ne, nbe, nbn);
    k_scan_p3<<<nbe + nbn, 256>>>(nn, ne, nbe);
    k_scatter<<<(nhalf + 255) / 256, 256>>>(nnz);
    k_edge_agg<<<(ne + 7) / 8, 256>>>((const float4*)x, ne);
    dim3 gg((ne + 63) / 64, DIM / 64);
    k_gemm<<<gg, 256>>>(W, ne);
    k_node_agg<<<(nn + 7) / 8, 256>>>(b, (float4*)d_out, nn);
}